// round 7
// baseline (speedup 1.0000x reference)
#include <cuda_runtime.h>
#include <cuda_fp16.h>
#include <cstdint>
#include <cstring>

// ---------------------------------------------------------------------------
// Problem constants
// ---------------------------------------------------------------------------
#define OUTF   11008
#define INF    4096
#define TOKENS 4096
#define NNZ_I  (OUTF * (INF / 2))      // 22544384

// GEMM tiling (mma.sync.m16n8k32 path — sm_100 baseline ISA)
#define BM 128
#define BN 128
#define BK 64
#define STAGES 4
#define KITERS (INF / BK)              // 64

// SMEM: per stage, A[128][64] + B[128][64] int8, rows padded to 80B
#define ROWB      80
#define TILE_B    (128 * ROWB)          // 10240
#define STAGE_B   (2 * TILE_B)          // 20480
#define SMEM_TOTAL (STAGES * STAGE_B)   // 81920

// ---------------------------------------------------------------------------
// Scratch device globals (allocation-free; zero-initialized at module load)
// ---------------------------------------------------------------------------
__device__ __align__(1024) int8_t g_w8[(size_t)OUTF * INF];   // dense int8 W
__device__ __align__(1024) int8_t g_xq[(size_t)TOKENS * INF]; // quantized x

// ---------------------------------------------------------------------------
// PTX helpers
// ---------------------------------------------------------------------------
__device__ __forceinline__ uint32_t smem_u32(const void* p) {
    uint32_t a;
    asm("{ .reg .u64 t; cvta.to.shared.u64 t, %1; cvt.u32.u64 %0, t; }"
        : "=r"(a) : "l"(p));
    return a;
}

__device__ __forceinline__ void cp16(uint32_t dst, const void* src) {
    asm volatile("cp.async.cg.shared.global [%0], [%1], 16;"
                 :: "r"(dst), "l"(src) : "memory");
}

__device__ __forceinline__ void ldsm4(uint32_t r[4], uint32_t addr) {
    asm volatile("ldmatrix.sync.aligned.m8n8.x4.shared.b16 {%0,%1,%2,%3}, [%4];"
                 : "=r"(r[0]), "=r"(r[1]), "=r"(r[2]), "=r"(r[3]) : "r"(addr));
}

__device__ __forceinline__ void mma_s8(int c[4], const uint32_t a[4],
                                       uint32_t b0, uint32_t b1) {
    asm volatile(
        "mma.sync.aligned.m16n8k32.row.col.s32.s8.s8.s32 "
        "{%0,%1,%2,%3}, {%4,%5,%6,%7}, {%8,%9}, {%0,%1,%2,%3};"
        : "+r"(c[0]), "+r"(c[1]), "+r"(c[2]), "+r"(c[3])
        : "r"(a[0]), "r"(a[1]), "r"(a[2]), "r"(a[3]), "r"(b0), "r"(b1));
}

// ---------------------------------------------------------------------------
// Kernel 1: per-tensor activation quantization (f32 in, int8 out)
// x_q = clip(rint(x/s) + o, -128, 127); IEEE div.rn matches reference exactly
// ---------------------------------------------------------------------------
__global__ void quant_kernel(const float* __restrict__ x,
                             const float* __restrict__ sc,
                             const int* __restrict__ off) {
    int i = blockIdx.x * blockDim.x + threadIdx.x;   // one thread per 4 elems
    float s = *sc;
    float o = (float)(*off);
    float4 v = reinterpret_cast<const float4*>(x)[i];
    float q0 = fminf(fmaxf(rintf(v.x / s) + o, -128.f), 127.f);
    float q1 = fminf(fmaxf(rintf(v.y / s) + o, -128.f), 127.f);
    float q2 = fminf(fmaxf(rintf(v.z / s) + o, -128.f), 127.f);
    float q3 = fminf(fmaxf(rintf(v.w / s) + o, -128.f), 127.f);
    char r[4] = { (char)(int)q0, (char)(int)q1, (char)(int)q2, (char)(int)q3 };
    uint32_t p;
    memcpy(&p, r, 4);
    reinterpret_cast<uint32_t*>(g_xq)[i] = p;
}

// ---------------------------------------------------------------------------
// Kernel 2: sparse decompress (sorted index, last-occurrence wins).
// Dtype probe: odd int32 slots mid-array are 0 only if data is int64
// (high words; max index < 2^31). Harness is expected to deliver int32.
// ---------------------------------------------------------------------------
__global__ void decomp_kernel(const int* __restrict__ vals,
                              const int* __restrict__ idx32, int nnz) {
    int i = blockIdx.x * blockDim.x + threadIdx.x;
    if (i >= nnz) return;
    const int p1 = (nnz / 2) | 1;
    const int p2 = (nnz / 4) | 1;
    const bool is64 = (idx32[p1] == 0) && (idx32[p2] == 0);
    long long p;
    bool dup;
    if (is64) {
        const long long* idx = (const long long*)idx32;
        p = idx[i];
        dup = (i + 1 < nnz) && (idx[i + 1] == p);
    } else {
        p = idx32[i];
        dup = (i + 1 < nnz) && (idx32[i + 1] == (int)p);
    }
    if (dup) return;                                  // later duplicate wins
    if (p < 0 || p >= (long long)OUTF * INF) return;  // insurance
    g_w8[p] = (int8_t)vals[i];
}

// ---------------------------------------------------------------------------
// Kernel 3: int8 GEMM (mma.sync m16n8k32) + bias + per-channel dequant
//   -> fp16-rounded values stored as f32
//   grid (OUTF/BN=86, TOKENS/BM=32), 256 threads, 2 CTAs/SM
// ---------------------------------------------------------------------------
__device__ __forceinline__ void load_stage(uint32_t stageBase,
                                           const int8_t* gA, const int8_t* gB,
                                           int k, int tid) {
    const int8_t* pA = gA + k * BK;
    const int8_t* pB = gB + k * BK;
#pragma unroll
    for (int u = 0; u < 2; u++) {
        int unit = u * 256 + tid;       // 512 16B-units per operand tile
        int row  = unit >> 2;           // 0..127
        int c16  = (unit & 3) * 16;     // 0,16,32,48
        cp16(stageBase + row * ROWB + c16,          pA + (size_t)row * INF + c16);
        cp16(stageBase + TILE_B + row * ROWB + c16, pB + (size_t)row * INF + c16);
    }
}

__global__ void __launch_bounds__(256, 2)
gemm_kernel(const float* __restrict__ dsc, const int* __restrict__ qb,
            float* __restrict__ out) {
    extern __shared__ char smem[];
    const uint32_t sb = smem_u32(smem);
    const int tid  = threadIdx.x;
    const int lane = tid & 31;
    const int warp = tid >> 5;
    const int wm   = warp & 1;          // 0..1 : M position (64 rows each)
    const int wn   = warp >> 1;         // 0..3 : N position (32 cols each)
    const int nBase = blockIdx.x * BN;
    const int mBase = blockIdx.y * BM;

    const int8_t* gA = g_xq + (size_t)mBase * INF;
    const int8_t* gB = g_w8 + (size_t)nBase * INF;

    // ldmatrix lane addressing (A: m16x32 tile as 4x m8n8.b16)
    const int subA = lane >> 3;
    const int rowA = (lane & 7) + (subA & 1) * 8;   // row within m16 tile
    const int colA = (subA >> 1) * 16;              // byte within 32B k-step
    // B: two n8xk32 tiles per ldmatrix.x4
    const int subB = lane >> 3;
    const int rowB = lane & 7;
    const int bTileAdd = subB >> 1;                 // 0/1 -> n-tile 2j / 2j+1
    const int bColAdd  = (subB & 1) * 16;

    int acc[4][4][4];
#pragma unroll
    for (int t = 0; t < 4; t++)
#pragma unroll
        for (int n = 0; n < 4; n++)
#pragma unroll
            for (int r = 0; r < 4; r++) acc[t][n][r] = 0;

    // prologue: fill 3 stages
#pragma unroll
    for (int k = 0; k < STAGES - 1; k++) {
        load_stage(sb + k * STAGE_B, gA, gB, k, tid);
        asm volatile("cp.async.commit_group;" ::: "memory");
    }

    for (int k = 0; k < KITERS; k++) {
        const int s = k & (STAGES - 1);
        asm volatile("cp.async.wait_group %0;" :: "n"(STAGES - 2) : "memory");
        __syncthreads();

        const uint32_t aS = sb + s * STAGE_B;
        const uint32_t bS = aS + TILE_B;

#pragma unroll
        for (int ks = 0; ks < 2; ks++) {
            uint32_t a[4][4];
#pragma unroll
            for (int t = 0; t < 4; t++)
                ldsm4(a[t], aS + (wm * 64 + t * 16 + rowA) * ROWB + ks * 32 + colA);
            uint32_t b[4][2];
#pragma unroll
            for (int j = 0; j < 2; j++) {
                uint32_t r[4];
                ldsm4(r, bS + (wn * 32 + (2 * j + bTileAdd) * 8 + rowB) * ROWB
                             + ks * 32 + bColAdd);
                b[2 * j][0] = r[0]; b[2 * j][1] = r[1];
                b[2 * j + 1][0] = r[2]; b[2 * j + 1][1] = r[3];
            }
#pragma unroll
            for (int t = 0; t < 4; t++)
#pragma unroll
                for (int n = 0; n < 4; n++)
                    mma_s8(acc[t][n], a[t], b[n][0], b[n][1]);
        }

        if (k + STAGES - 1 < KITERS) {
            load_stage(sb + ((k + STAGES - 1) & (STAGES - 1)) * STAGE_B,
                       gA, gB, k + STAGES - 1, tid);
        }
        asm volatile("cp.async.commit_group;" ::: "memory");
    }

    // ---------------- epilogue: dequant, fp16 round, store f32 ----------------
    const int tig = lane & 3;
    const int gid = lane >> 2;
    float sc[4][2];
    int   bi[4][2];
#pragma unroll
    for (int n = 0; n < 4; n++) {
        int col = nBase + wn * 32 + n * 8 + tig * 2;
        sc[n][0] = dsc[col];     sc[n][1] = dsc[col + 1];
        bi[n][0] = qb[col];      bi[n][1] = qb[col + 1];
    }
#pragma unroll
    for (int t = 0; t < 4; t++) {
        int row0 = mBase + wm * 64 + t * 16 + gid;
#pragma unroll
        for (int n = 0; n < 4; n++) {
            int col = nBase + wn * 32 + n * 8 + tig * 2;
            float f0 = (float)(acc[t][n][0] + bi[n][0]) * sc[n][0];
            float f1 = (float)(acc[t][n][1] + bi[n][1]) * sc[n][1];
            float f2 = (float)(acc[t][n][2] + bi[n][0]) * sc[n][0];
            float f3 = (float)(acc[t][n][3] + bi[n][1]) * sc[n][1];
            // reference result dtype is fp16 -> round through fp16
            float2 r0 = make_float2(__half2float(__float2half_rn(f0)),
                                    __half2float(__float2half_rn(f1)));
            float2 r1 = make_float2(__half2float(__float2half_rn(f2)),
                                    __half2float(__float2half_rn(f3)));
            *reinterpret_cast<float2*>(out + (size_t)row0 * OUTF + col) = r0;
            *reinterpret_cast<float2*>(out + (size_t)(row0 + 8) * OUTF + col) = r1;
        }
    }
}

// ---------------------------------------------------------------------------
// Launcher
// ---------------------------------------------------------------------------
extern "C" void kernel_launch(void* const* d_in, const int* in_sizes, int n_in,
                              void* d_out, int out_size) {
    (void)in_sizes; (void)n_in; (void)out_size;
    const float* x    = (const float*)d_in[0];   // fp16 promoted to f32
    const int*   wv   = (const int*)d_in[1];
    const int*   idx  = (const int*)d_in[2];     // int64 demoted to int32
    const float* isc  = (const float*)d_in[3];   // fp16 promoted to f32
    const int*   ioff = (const int*)d_in[4];
    const float* dsc  = (const float*)d_in[5];
    const int*   qb   = (const int*)d_in[6];
    float*       out  = (float*)d_out;           // fp16 promoted to f32

    quant_kernel<<<(TOKENS * INF / 4) / 256, 256>>>(x, isc, ioff);
    decomp_kernel<<<(NNZ_I + 255) / 256, 256>>>(wv, idx, NNZ_I);

    cudaFuncSetAttribute(gemm_kernel,
                         cudaFuncAttributeMaxDynamicSharedMemorySize, SMEM_TOTAL);
    gemm_kernel<<<dim3(OUTF / BN, TOKENS / BM), 256, SMEM_TOTAL>>>(dsc, qb, out);
}

// round 9
// speedup vs baseline: 1.2722x; 1.2722x over previous
#include <cuda_runtime.h>
#include <cuda_fp16.h>
#include <cstdint>
#include <cstring>

// ---------------------------------------------------------------------------
// Problem constants
// ---------------------------------------------------------------------------
#define OUTF   11008
#define INF    4096
#define TOKENS 4096
#define NNZ_I  (OUTF * (INF / 2))      // 22544384

// GEMM tiling (mma.sync.m16n8k32 path — sm_100 baseline ISA)
#define BM 128
#define BN 128
#define BK 128
#define STAGES 3
#define KITERS (INF / BK)              // 32

// SMEM: per stage, A[128][128] + B[128][128] int8, rows padded to 144B
// (144B stride: row r starts at bank (4r)%32; 8-row ldmatrix touches all 32
//  banks exactly once -> conflict-free, for both 16B column chunks)
#define ROWB      144
#define TILE_B    (128 * ROWB)          // 18432
#define STAGE_B   (2 * TILE_B)          // 36864
#define SMEM_TOTAL (STAGES * STAGE_B)   // 110592  (2 CTAs/SM: 221184 < 227KB)

// prep kernel split
#define QBLOCKS   (TOKENS * INF / 4 / 256)   // 16384 quant blocks
#define DBLOCKS   (NNZ_I / 4 / 256)          // 22016 decomp blocks (exact)

// ---------------------------------------------------------------------------
// Scratch device globals (allocation-free; zero-initialized at module load)
// ---------------------------------------------------------------------------
__device__ __align__(1024) int8_t g_w8[(size_t)OUTF * INF];   // dense int8 W
__device__ __align__(1024) int8_t g_xq[(size_t)TOKENS * INF]; // quantized x

// ---------------------------------------------------------------------------
// PTX helpers
// ---------------------------------------------------------------------------
__device__ __forceinline__ uint32_t smem_u32(const void* p) {
    uint32_t a;
    asm("{ .reg .u64 t; cvta.to.shared.u64 t, %1; cvt.u32.u64 %0, t; }"
        : "=r"(a) : "l"(p));
    return a;
}

__device__ __forceinline__ void cp16(uint32_t dst, const void* src) {
    asm volatile("cp.async.cg.shared.global [%0], [%1], 16;"
                 :: "r"(dst), "l"(src) : "memory");
}

__device__ __forceinline__ void ldsm4(uint32_t r[4], uint32_t addr) {
    asm volatile("ldmatrix.sync.aligned.m8n8.x4.shared.b16 {%0,%1,%2,%3}, [%4];"
                 : "=r"(r[0]), "=r"(r[1]), "=r"(r[2]), "=r"(r[3]) : "r"(addr));
}

__device__ __forceinline__ void mma_s8(int c[4], const uint32_t a[4],
                                       uint32_t b0, uint32_t b1) {
    asm volatile(
        "mma.sync.aligned.m16n8k32.row.col.s32.s8.s8.s32 "
        "{%0,%1,%2,%3}, {%4,%5,%6,%7}, {%8,%9}, {%0,%1,%2,%3};"
        : "+r"(c[0]), "+r"(c[1]), "+r"(c[2]), "+r"(c[3])
        : "r"(a[0]), "r"(a[1]), "r"(a[2]), "r"(a[3]), "r"(b0), "r"(b1));
}

// ---------------------------------------------------------------------------
// Kernel 1 (fused prep): blocks [0, QBLOCKS) quantize activations,
// blocks [QBLOCKS, QBLOCKS+DBLOCKS) decompress the sparse weight.
// ---------------------------------------------------------------------------
__global__ void prep_kernel(const float* __restrict__ x,
                            const float* __restrict__ sc,
                            const int* __restrict__ off,
                            const int* __restrict__ vals,
                            const int* __restrict__ idx32) {
    const int bid = blockIdx.x;
    const int tid = threadIdx.x;

    if (bid < QBLOCKS) {
        // ---- per-tensor activation quantization (f32 in, int8 out) ----
        int i = bid * 256 + tid;            // one thread per 4 elems
        float s = *sc;
        float o = (float)(*off);
        float4 v = reinterpret_cast<const float4*>(x)[i];
        float q0 = fminf(fmaxf(rintf(v.x / s) + o, -128.f), 127.f);
        float q1 = fminf(fmaxf(rintf(v.y / s) + o, -128.f), 127.f);
        float q2 = fminf(fmaxf(rintf(v.z / s) + o, -128.f), 127.f);
        float q3 = fminf(fmaxf(rintf(v.w / s) + o, -128.f), 127.f);
        char r[4] = { (char)(int)q0, (char)(int)q1, (char)(int)q2, (char)(int)q3 };
        uint32_t p;
        memcpy(&p, r, 4);
        reinterpret_cast<uint32_t*>(g_xq)[i] = p;
    } else {
        // ---- sparse decompress: 4 entries/thread, last-duplicate wins ----
        const int base = ((bid - QBLOCKS) * 256 + tid) * 4;
        // dtype probe (int64 high words are 0; int32 sorted mid values aren't)
        const int p1 = (NNZ_I / 2) | 1;
        const int p2 = (NNZ_I / 4) | 1;
        const bool is64 = (idx32[p1] == 0) && (idx32[p2] == 0);
        if (!is64) {
            int4 vi = *reinterpret_cast<const int4*>(idx32 + base);
            int4 vv = *reinterpret_cast<const int4*>(vals + base);
            int id[4] = { vi.x, vi.y, vi.z, vi.w };
            int vl[4] = { vv.x, vv.y, vv.z, vv.w };
#pragma unroll
            for (int j = 0; j < 4; j++) {
                int g = base + j;
                int nxt = (j < 3) ? id[j + 1]
                                  : ((g + 1 < NNZ_I) ? idx32[g + 1] : -1);
                if (nxt == id[j]) continue;          // later duplicate wins
                if (id[j] < 0 || id[j] >= OUTF * INF) continue;
                g_w8[id[j]] = (int8_t)vl[j];
            }
        } else {
            const long long* idx = (const long long*)idx32;
#pragma unroll
            for (int j = 0; j < 4; j++) {
                int g = base + j;
                long long p = idx[g];
                if (g + 1 < NNZ_I && idx[g + 1] == p) continue;
                if (p < 0 || p >= (long long)OUTF * INF) continue;
                g_w8[p] = (int8_t)vals[g];
            }
        }
    }
}

// ---------------------------------------------------------------------------
// Kernel 2: int8 GEMM (mma.sync m16n8k32) + bias + per-channel dequant
//   -> fp16-rounded values stored as f32
//   grid (OUTF/BN=86, TOKENS/BM=32), 256 threads, 2 CTAs/SM
// ---------------------------------------------------------------------------
__device__ __forceinline__ void load_stage(uint32_t stageBase,
                                           const int8_t* gA, const int8_t* gB,
                                           int k, int tid) {
    const int8_t* pA = gA + k * BK;
    const int8_t* pB = gB + k * BK;
#pragma unroll
    for (int u = 0; u < 4; u++) {
        int unit = u * 256 + tid;       // 1024 16B-units per operand tile
        int row  = unit >> 3;           // 0..127
        int c16  = (unit & 7) * 16;     // 0..112
        cp16(stageBase + row * ROWB + c16,          pA + (size_t)row * INF + c16);
        cp16(stageBase + TILE_B + row * ROWB + c16, pB + (size_t)row * INF + c16);
    }
}

__global__ void __launch_bounds__(256, 2)
gemm_kernel(const float* __restrict__ dsc, const int* __restrict__ qb,
            float* __restrict__ out) {
    extern __shared__ char smem[];
    const uint32_t sb = smem_u32(smem);
    const int tid  = threadIdx.x;
    const int lane = tid & 31;
    const int warp = tid >> 5;
    const int wm   = warp & 1;          // 0..1 : M position (64 rows each)
    const int wn   = warp >> 1;         // 0..3 : N position (32 cols each)
    const int nBase = blockIdx.x * BN;
    const int mBase = blockIdx.y * BM;

    const int8_t* gA = g_xq + (size_t)mBase * INF;
    const int8_t* gB = g_w8 + (size_t)nBase * INF;

    // ldmatrix lane addressing (A: m16x32 tile as 4x m8n8.b16)
    const int subA = lane >> 3;
    const int rowA = (lane & 7) + (subA & 1) * 8;   // row within m16 tile
    const int colA = (subA >> 1) * 16;              // byte within 32B k-step
    // B: two n8xk32 tiles per ldmatrix.x4
    const int subB = lane >> 3;
    const int rowB = lane & 7;
    const int bTileAdd = subB >> 1;                 // 0/1 -> n-tile 2j / 2j+1
    const int bColAdd  = (subB & 1) * 16;

    int acc[4][4][4];
#pragma unroll
    for (int t = 0; t < 4; t++)
#pragma unroll
        for (int n = 0; n < 4; n++)
#pragma unroll
            for (int r = 0; r < 4; r++) acc[t][n][r] = 0;

    // prologue: fill STAGES-1 stages
#pragma unroll
    for (int k = 0; k < STAGES - 1; k++) {
        load_stage(sb + k * STAGE_B, gA, gB, k, tid);
        asm volatile("cp.async.commit_group;" ::: "memory");
    }

    for (int k = 0; k < KITERS; k++) {
        const int s = k % STAGES;
        asm volatile("cp.async.wait_group %0;" :: "n"(STAGES - 2) : "memory");
        __syncthreads();

        const uint32_t aS = sb + s * STAGE_B;
        const uint32_t bS = aS + TILE_B;

#pragma unroll
        for (int ks = 0; ks < 4; ks++) {            // 4 x k32 per BK=128
            uint32_t a[4][4];
#pragma unroll
            for (int t = 0; t < 4; t++)
                ldsm4(a[t], aS + (wm * 64 + t * 16 + rowA) * ROWB + ks * 32 + colA);
            uint32_t b[4][2];
#pragma unroll
            for (int j = 0; j < 2; j++) {
                uint32_t r[4];
                ldsm4(r, bS + (wn * 32 + (2 * j + bTileAdd) * 8 + rowB) * ROWB
                             + ks * 32 + bColAdd);
                b[2 * j][0] = r[0]; b[2 * j][1] = r[1];
                b[2 * j + 1][0] = r[2]; b[2 * j + 1][1] = r[3];
            }
#pragma unroll
            for (int t = 0; t < 4; t++)
#pragma unroll
                for (int n = 0; n < 4; n++)
                    mma_s8(acc[t][n], a[t], b[n][0], b[n][1]);
        }

        if (k + STAGES - 1 < KITERS) {
            load_stage(sb + ((k + STAGES - 1) % STAGES) * STAGE_B,
                       gA, gB, k + STAGES - 1, tid);
        }
        asm volatile("cp.async.commit_group;" ::: "memory");
    }

    // ---------------- epilogue: dequant, fp16 round, store f32 ----------------
    const int tig = lane & 3;
    const int gid = lane >> 2;
    float sc[4][2];
    int   bi[4][2];
#pragma unroll
    for (int n = 0; n < 4; n++) {
        int col = nBase + wn * 32 + n * 8 + tig * 2;
        sc[n][0] = dsc[col];     sc[n][1] = dsc[col + 1];
        bi[n][0] = qb[col];      bi[n][1] = qb[col + 1];
    }
#pragma unroll
    for (int t = 0; t < 4; t++) {
        int row0 = mBase + wm * 64 + t * 16 + gid;
#pragma unroll
        for (int n = 0; n < 4; n++) {
            int col = nBase + wn * 32 + n * 8 + tig * 2;
            float f0 = (float)(acc[t][n][0] + bi[n][0]) * sc[n][0];
            float f1 = (float)(acc[t][n][1] + bi[n][1]) * sc[n][1];
            float f2 = (float)(acc[t][n][2] + bi[n][0]) * sc[n][0];
            float f3 = (float)(acc[t][n][3] + bi[n][1]) * sc[n][1];
            // reference result dtype is fp16 -> round through fp16
            float2 r0 = make_float2(__half2float(__float2half_rn(f0)),
                                    __half2float(__float2half_rn(f1)));
            float2 r1 = make_float2(__half2float(__float2half_rn(f2)),
                                    __half2float(__float2half_rn(f3)));
            *reinterpret_cast<float2*>(out + (size_t)row0 * OUTF + col) = r0;
            *reinterpret_cast<float2*>(out + (size_t)(row0 + 8) * OUTF + col) = r1;
        }
    }
}

// ---------------------------------------------------------------------------
// Launcher
// ---------------------------------------------------------------------------
extern "C" void kernel_launch(void* const* d_in, const int* in_sizes, int n_in,
                              void* d_out, int out_size) {
    (void)in_sizes; (void)n_in; (void)out_size;
    const float* x    = (const float*)d_in[0];   // fp16 promoted to f32
    const int*   wv   = (const int*)d_in[1];
    const int*   idx  = (const int*)d_in[2];     // int64 demoted to int32
    const float* isc  = (const float*)d_in[3];   // fp16 promoted to f32
    const int*   ioff = (const int*)d_in[4];
    const float* dsc  = (const float*)d_in[5];
    const int*   qb   = (const int*)d_in[6];
    float*       out  = (float*)d_out;           // fp16 promoted to f32

    prep_kernel<<<QBLOCKS + DBLOCKS, 256>>>(x, isc, ioff, wv, idx);

    cudaFuncSetAttribute(gemm_kernel,
                         cudaFuncAttributeMaxDynamicSharedMemorySize, SMEM_TOTAL);
    gemm_kernel<<<dim3(OUTF / BN, TOKENS / BM), 256, SMEM_TOTAL>>>(dsc, qb, out);
}